// round 17
// baseline (speedup 1.0000x reference)
#include <cuda_runtime.h>
#include <cstdint>
#include <cstddef>

// MultiInputLSTMCell, sm_103a. B=16384, X=50, CIN=128, H=128.
// Pipeline (fast case, identities hold):
//   prep1(128)  : identity checks + weight pre-transform + count histograms
//   scatter(128): descending counting-sort permutation + publish id flags
//   phaseA(256) : tf32-mma gates/valpha -> interleaved 33.5MB scratch
//   phaseB(1024): per-row elementwise softmax-mix; skip_c streamed evict-first
//   fused(256)  : full fallback, early-exits when identities hold

#define BTOT 16384
#define XDIM 50
#define CINV 128
#define HV   128
#define TM   64
#define STR  132
#define NT   256
#define NBINS (XDIM + 1)
#define P1CTAS 128
#define SEG   (BTOT / P1CTAS)
#define BWELE (64 * STR * 2)
#define BWCHUNK (BWELE / 4)
#define BWARPS 8192

__device__ int d_perm[BTOT];
__device__ int d_id_hh;
__device__ int d_id_a;
__device__ int d_hist_part[P1CTAS * NBINS];
__device__ int d_ok_part[P1CTAS * 2];
__device__ uint4 d_wtf[4][BWCHUNK];
// interleaved per-row scratch: [row][field][HV], field 0=va 1=ei 2=nm 3=ov
__device__ float d_sc[(size_t)BTOT * 4 * HV];

// ---------------------------------------------------------------------------
__device__ __forceinline__ uint32_t f2tf(float f) {
    uint32_t r; asm("cvt.rna.tf32.f32 %0, %1;" : "=r"(r) : "f"(f)); return r;
}
__device__ __forceinline__ void mma8(float* c, uint32_t a0, uint32_t a1, uint32_t a2, uint32_t a3,
                                     uint32_t b0, uint32_t b1) {
    asm volatile("mma.sync.aligned.m16n8k8.row.col.f32.tf32.tf32.f32 "
                 "{%0,%1,%2,%3}, {%4,%5,%6,%7}, {%8,%9}, {%0,%1,%2,%3};"
                 : "+f"(c[0]), "+f"(c[1]), "+f"(c[2]), "+f"(c[3])
                 : "r"(a0), "r"(a1), "r"(a2), "r"(a3), "r"(b0), "r"(b1));
}
__device__ __forceinline__ void cpasync16(void* s, const void* g) {
    uint32_t sa = (uint32_t)__cvta_generic_to_shared(s);
    asm volatile("cp.async.cg.shared.global [%0], [%1], 16;" :: "r"(sa), "l"(g));
}
__device__ __forceinline__ void cpcommit() { asm volatile("cp.async.commit_group;"); }
template <int N> __device__ __forceinline__ void cpwait() {
    asm volatile("cp.async.wait_group %0;" :: "n"(N));
}
__device__ __forceinline__ float sigmf(float x) {
    return __fdividef(1.0f, 1.0f + __expf(-x));
}
__device__ __forceinline__ float tanhapx(float x) {
    float t; asm("tanh.approx.f32 %0, %1;" : "=f"(t) : "f"(x)); return t;
}
__device__ __forceinline__ float ex2apx(float x) {
    float t; asm("ex2.approx.f32 %0, %1;" : "=f"(t) : "f"(x)); return t;
}
__device__ __forceinline__ float wfast(float z) {          // exp(sigmoid(z))
    return __expf(fmaf(tanhapx(z * 0.5f), 0.5f, 0.5f));
}
// streaming (evict-first) float4 load/store
__device__ __forceinline__ float4 ldcs4(const float4* p) {
    float4 v;
    asm volatile("ld.global.cs.v4.f32 {%0,%1,%2,%3}, [%4];"
                 : "=f"(v.x), "=f"(v.y), "=f"(v.z), "=f"(v.w) : "l"(p));
    return v;
}
__device__ __forceinline__ void stcs4(float4* p, float4 v) {
    asm volatile("st.global.cs.v4.f32 [%0], {%1,%2,%3,%4};"
                 :: "l"(p), "f"(v.x), "f"(v.y), "f"(v.z), "f"(v.w) : "memory");
}

__device__ __forceinline__ void stageB(const float* __restrict__ g, int stride,
                                       uint32_t* __restrict__ bw, int tid) {
    #pragma unroll 4
    for (int idx = tid; idx < 128 * 128; idx += NT) {
        int k = idx >> 7, n = idx & 127;
        uint32_t t = f2tf(g[k * stride + n]);
        int ks = k >> 3, mm = k & 7;
        bw[(((ks << 2) + (mm & 3)) * STR + n) * 2 + (mm >> 2)] = t;
    }
}
__device__ __forceinline__ void stage_async(uint32_t* bw, const uint4* src, int tid) {
    uint4* dst = (uint4*)bw;
    for (int i = tid; i < BWCHUNK; i += NT)
        cpasync16(dst + i, src + i);
    cpcommit();
}
__device__ __forceinline__ void gemm_tile(const float* __restrict__ SA,
                                          const float2* __restrict__ BW,
                                          float (&acc)[32], int warpM, int warpN, int lane) {
    int g = lane >> 2, m = lane & 3;
    const float* Ap = SA + (warpM * 32 + g) * STR + m;
    const float2* Bp0 = BW + (size_t)m * STR + warpN * 32 + g;
    #pragma unroll
    for (int ks = 0; ks < 16; ks++) {
        int kc = ks * 8;
        uint32_t a00 = f2tf(Ap[kc]);
        uint32_t a01 = f2tf(Ap[8 * STR + kc]);
        uint32_t a02 = f2tf(Ap[kc + 4]);
        uint32_t a03 = f2tf(Ap[8 * STR + kc + 4]);
        uint32_t a10 = f2tf(Ap[16 * STR + kc]);
        uint32_t a11 = f2tf(Ap[24 * STR + kc]);
        uint32_t a12 = f2tf(Ap[16 * STR + kc + 4]);
        uint32_t a13 = f2tf(Ap[24 * STR + kc + 4]);
        const float2* Bp = Bp0 + (size_t)(ks * 4) * STR;
        #pragma unroll
        for (int j = 0; j < 4; j++) {
            float2 b = Bp[j * 8];
            uint32_t b0 = __float_as_uint(b.x), b1 = __float_as_uint(b.y);
            mma8(&acc[j * 4],      a00, a01, a02, a03, b0, b1);
            mma8(&acc[16 + j * 4], a10, a11, a12, a13, b0, b1);
        }
    }
}

// ---------------------------------------------------------------------------
// prep1: identity checks + histograms + weight pre-transform. 128 CTAs.
// ---------------------------------------------------------------------------
__global__ void prep1_kernel(const int* __restrict__ cnt,
                             const float* __restrict__ w_hh,
                             const float* __restrict__ a_whh,
                             const float* __restrict__ w_ih,
                             const float* __restrict__ a_wih) {
    __shared__ int h[NBINS];
    int tid = threadIdx.x, cta = blockIdx.x;
    int gtid = cta * 256 + tid;

    int okhh = 1, oka = 1;
    const float4* w4 = (const float4*)w_hh;
    for (int i = gtid; i < 128 * 384 / 4; i += P1CTAS * 256) {
        int l = i * 4;
        int k = l / 384, c0 = l % 384;
        float4 v = w4[i];
        okhh &= (v.x == (((c0 + 0) & 127) == k ? 1.f : 0.f));
        okhh &= (v.y == (((c0 + 1) & 127) == k ? 1.f : 0.f));
        okhh &= (v.z == (((c0 + 2) & 127) == k ? 1.f : 0.f));
        okhh &= (v.w == (((c0 + 3) & 127) == k ? 1.f : 0.f));
    }
    const float4* a4 = (const float4*)a_whh;
    for (int i = gtid; i < 128 * 128 / 4; i += P1CTAS * 256) {
        int l = i * 4;
        int k = l >> 7, c0 = l & 127;
        float4 v = a4[i];
        oka &= (v.x == ((c0 + 0) == k ? 1.f : 0.f));
        oka &= (v.y == ((c0 + 1) == k ? 1.f : 0.f));
        oka &= (v.z == ((c0 + 2) == k ? 1.f : 0.f));
        oka &= (v.w == ((c0 + 3) == k ? 1.f : 0.f));
    }
    for (int i = gtid; i < 4 * 128 * 128; i += P1CTAS * 256) {
        int p = i >> 14, idx = i & 16383;
        int k = idx >> 7, n = idx & 127;
        const float* src = (p < 3) ? (w_ih + p * 128) : a_wih;
        int stride = (p < 3) ? 384 : 128;
        uint32_t t = f2tf(src[k * stride + n]);
        int ks = k >> 3, mm = k & 7;
        ((uint32_t*)d_wtf[p])[(((ks << 2) + (mm & 3)) * STR + n) * 2 + (mm >> 2)] = t;
    }

    if (tid < NBINS) h[tid] = 0;
    __syncthreads();
    if (tid < SEG) {
        int b = cta * SEG + tid;
        int v = cnt[b]; if (v < 0) v = 0; if (v > XDIM) v = XDIM;
        atomicAdd(&h[v], 1);
    }
    okhh = __syncthreads_and(okhh);
    oka  = __syncthreads_and(oka);
    if (tid == 0) { d_ok_part[cta * 2] = okhh; d_ok_part[cta * 2 + 1] = oka; }
    if (tid < NBINS) d_hist_part[cta * NBINS + tid] = h[tid];
}

// ---------------------------------------------------------------------------
// scatter: redundant reduce+scan per CTA, disjoint scatter; CTA0 publishes flags
// ---------------------------------------------------------------------------
__global__ void prep_scatter_kernel(const int* __restrict__ cnt) {
    __shared__ int tot[NBINS];
    __shared__ int basev[NBINS];
    __shared__ int cur[NBINS];
    int tid = threadIdx.x, cta = blockIdx.x;

    if (cta == 0 && tid == 0) {
        int a = 1, b = 1;
        for (int c = 0; c < P1CTAS; c++) { a &= d_ok_part[2 * c]; b &= d_ok_part[2 * c + 1]; }
        d_id_hh = a; d_id_a = b;
    }
    if (tid < NBINS) {
        int s = 0, pre = 0;
        for (int c = 0; c < P1CTAS; c++) {
            int hp = d_hist_part[c * NBINS + tid];
            if (c < cta) pre += hp;
            s += hp;
        }
        tot[tid] = s;
        cur[tid] = pre;
    }
    __syncthreads();
    if (tid == 0) {
        int acc = 0;
        for (int v = XDIM; v >= 0; v--) { basev[v] = acc; acc += tot[v]; }
    }
    __syncthreads();
    if (tid < NBINS) cur[tid] += basev[tid];
    __syncthreads();
    if (tid < SEG) {
        int b = cta * SEG + tid;
        int v = cnt[b]; if (v < 0) v = 0; if (v > XDIM) v = XDIM;
        int pos = atomicAdd(&cur[v], 1);
        d_perm[pos] = b;
    }
}

// ---------------------------------------------------------------------------
// phase A (fast path only): gates + valpha via tf32 mma -> interleaved scratch
// ---------------------------------------------------------------------------
__global__ void __launch_bounds__(NT, 1) phaseA_kernel(
    const float* __restrict__ inp, const float* __restrict__ h0,
    const float* __restrict__ bias, const float* __restrict__ a_bias) {
    if (!(d_id_hh & d_id_a)) return;
    extern __shared__ char smem[];
    uint32_t* BW0u = (uint32_t*)smem;
    float2*   BW0  = (float2*)smem;
    uint32_t* BW1u = BW0u + BWELE;
    float2*   BW1  = (float2*)(smem + BWELE * 4);
    float* SA0 = (float*)(smem + 2 * BWELE * 4);
    float* SA1 = SA0 + TM * STR;

    int tid = threadIdx.x, lane = tid & 31, wid = tid >> 5;
    int warpM = wid & 1, warpN = wid >> 1;
    int base = blockIdx.x * TM;
    int g = lane >> 2, m = lane & 3;

    stage_async(BW0u, d_wtf[0], tid);
    stage_async(BW1u, d_wtf[1], tid);
    for (int idx = tid; idx < TM * 32; idx += NT) {
        int r = idx >> 5, c = (idx & 31) << 2;
        *(float4*)&SA0[r * STR + c] = *(const float4*)&inp[(size_t)(base + r) * CINV + c];
        *(float4*)&SA1[r * STR + c] = *(const float4*)&h0[(size_t)(base + r) * HV + c];
    }
    __syncthreads();

    float denom[32], num[32], ov[32], valpha[32], acc[32];
    #pragma unroll 1
    for (int p = 0; p < 4; p++) {
        if (p < 3) cpwait<1>(); else cpwait<0>();
        __syncthreads();
        #pragma unroll
        for (int q = 0; q < 32; q++) acc[q] = 0.f;
        gemm_tile(SA0, (p & 1) ? BW1 : BW0, acc, warpM, warpN, lane);
        #pragma unroll
        for (int j = 0; j < 4; j++) {
            int col = warpN * 32 + j * 8 + m * 2;
            float b0, b1;
            if (p < 3) { b0 = bias[p * 128 + col]; b1 = bias[p * 128 + col + 1]; }
            else       { b0 = a_bias[col];         b1 = a_bias[col + 1]; }
            #pragma unroll
            for (int mi = 0; mi < 2; mi++) {
                int o0 = mi * 16 + j * 4;
                int rlo = warpM * 32 + mi * 16 + g;
                float h0a = 0.f, h0b = 0.f, h0c = 0.f, h0d = 0.f;
                if (p < 3) {
                    float2 hlo = *(const float2*)&SA1[rlo * STR + col];
                    float2 hhi = *(const float2*)&SA1[(rlo + 8) * STR + col];
                    h0a = hlo.x; h0b = hlo.y; h0c = hhi.x; h0d = hhi.y;
                }
                float z0 = acc[o0 + 0] + b0 + h0a, z1 = acc[o0 + 1] + b1 + h0b;
                float z2 = acc[o0 + 2] + b0 + h0c, z3 = acc[o0 + 3] + b1 + h0d;
                if (p == 0) {
                    denom[o0 + 0] = __expf(sigmf(z0));
                    denom[o0 + 1] = __expf(sigmf(z1));
                    denom[o0 + 2] = __expf(sigmf(z2));
                    denom[o0 + 3] = __expf(sigmf(z3));
                } else if (p == 1) {
                    ov[o0 + 0] = sigmf(z0); ov[o0 + 1] = sigmf(z1);
                    ov[o0 + 2] = sigmf(z2); ov[o0 + 3] = sigmf(z3);
                } else if (p == 2) {
                    num[o0 + 0] = tanhf(z0) * denom[o0 + 0];
                    num[o0 + 1] = tanhf(z1) * denom[o0 + 1];
                    num[o0 + 2] = tanhf(z2) * denom[o0 + 2];
                    num[o0 + 3] = tanhf(z3) * denom[o0 + 3];
                } else {
                    valpha[o0 + 0] = z0; valpha[o0 + 1] = z1;
                    valpha[o0 + 2] = z2; valpha[o0 + 3] = z3;
                }
            }
        }
        __syncthreads();
        if (p < 2) stage_async((p & 1) ? BW1u : BW0u, d_wtf[p + 2], tid);
    }

    // store interleaved scratch: d_sc[row][field][HV], field 0=va 1=ei 2=nm 3=ov
    #pragma unroll
    for (int mi = 0; mi < 2; mi++) {
        int rlo = warpM * 32 + mi * 16 + g;
        size_t r0 = (size_t)(base + rlo) * 4 * HV;
        size_t r1 = (size_t)(base + rlo + 8) * 4 * HV;
        #pragma unroll
        for (int j = 0; j < 4; j++) {
            int o0 = mi * 16 + j * 4;
            int colb = warpN * 32 + j * 8 + m * 2;
            *(float2*)&d_sc[r0 + 0 * HV + colb] = make_float2(valpha[o0 + 0], valpha[o0 + 1]);
            *(float2*)&d_sc[r1 + 0 * HV + colb] = make_float2(valpha[o0 + 2], valpha[o0 + 3]);
            *(float2*)&d_sc[r0 + 1 * HV + colb] = make_float2(denom[o0 + 0], denom[o0 + 1]);
            *(float2*)&d_sc[r1 + 1 * HV + colb] = make_float2(denom[o0 + 2], denom[o0 + 3]);
            *(float2*)&d_sc[r0 + 2 * HV + colb] = make_float2(num[o0 + 0], num[o0 + 1]);
            *(float2*)&d_sc[r1 + 2 * HV + colb] = make_float2(num[o0 + 2], num[o0 + 3]);
            *(float2*)&d_sc[r0 + 3 * HV + colb] = make_float2(ov[o0 + 0], ov[o0 + 1]);
            *(float2*)&d_sc[r1 + 3 * HV + colb] = make_float2(ov[o0 + 2], ov[o0 + 3]);
        }
    }
}

// ---------------------------------------------------------------------------
// phase B (fast path only): one warp per row, sorted-pair balancing.
// skip_c loads use .cs (streaming / evict-first); scratch reads hit L2.
// ---------------------------------------------------------------------------
__global__ void __launch_bounds__(256) phaseB_kernel(
    const float* __restrict__ skip_c, const int* __restrict__ skip_count,
    float* __restrict__ out) {
    if (!(d_id_hh & d_id_a)) return;
    int w = blockIdx.x * 8 + (threadIdx.x >> 5);
    int lane = threadIdx.x & 31;
    int col = lane * 4;
    const float LC = 0.72134752f;    // 0.5*log2(e)

    int r0 = d_perm[w];
    int r1 = d_perm[BTOT - 1 - w];
    int rows[2] = {r0, r1};
    int c0 = skip_count[r0]; if (c0 < 0) c0 = 0; if (c0 > XDIM) c0 = XDIM;
    int c1r = skip_count[r1]; if (c1r < 0) c1r = 0; if (c1r > XDIM) c1r = XDIM;
    int cnts[2] = {c0, c1r};
    const float4* sps[2] = {
        (const float4*)(skip_c + (size_t)r0 * XDIM * HV) + lane,
        (const float4*)(skip_c + (size_t)r1 * XDIM * HV) + lane};
    float4 head[2];
    head[0] = make_float4(0.f, 0.f, 0.f, 0.f);
    head[1] = make_float4(0.f, 0.f, 0.f, 0.f);
    if (c0 > 0)  head[0] = ldcs4(sps[0]);
    if (c1r > 0) head[1] = ldcs4(sps[1]);

    #pragma unroll 1
    for (int half = 0; half < 2; half++) {
        int r = rows[half];
        int c = cnts[half];
        size_t sb = (size_t)r * 4 * HV;           // interleaved scratch base
        float4 va  = *(const float4*)&d_sc[sb + 0 * HV + col];
        float4 den = *(const float4*)&d_sc[sb + 1 * HV + col];
        float4 nm  = *(const float4*)&d_sc[sb + 2 * HV + col];
        float hv0 = va.x * 0.5f, hv1 = va.y * 0.5f, hv2 = va.z * 0.5f, hv3 = va.w * 0.5f;
        const float4* sp = sps[half];

        float4 s = head[half];
        for (int x = 0; x < c; x++) {
            float4 sn = s;
            if (x + 1 < c) sn = ldcs4(sp + (size_t)(x + 1) * 32);
            float w0 = ex2apx(fmaf(tanhapx(fmaf(s.x, 0.5f, hv0)), LC, LC));
            float w1 = ex2apx(fmaf(tanhapx(fmaf(s.y, 0.5f, hv1)), LC, LC));
            float w2 = ex2apx(fmaf(tanhapx(fmaf(s.z, 0.5f, hv2)), LC, LC));
            float w3 = ex2apx(fmaf(tanhapx(fmaf(s.w, 0.5f, hv3)), LC, LC));
            den.x += w0; den.y += w1; den.z += w2; den.w += w3;
            nm.x = fmaf(s.x, w0, nm.x); nm.y = fmaf(s.y, w1, nm.y);
            nm.z = fmaf(s.z, w2, nm.z); nm.w = fmaf(s.w, w3, nm.w);
            s = sn;
        }

        float4 ovv = *(const float4*)&d_sc[sb + 3 * HV + col];
        size_t rb = (size_t)r * HV;
        float4 c1, h1;
        c1.x = __fdividef(nm.x, den.x); c1.y = __fdividef(nm.y, den.y);
        c1.z = __fdividef(nm.z, den.z); c1.w = __fdividef(nm.w, den.w);
        h1.x = ovv.x * tanhf(c1.x); h1.y = ovv.y * tanhf(c1.y);
        h1.z = ovv.z * tanhf(c1.z); h1.w = ovv.w * tanhf(c1.w);
        stcs4((float4*)&out[rb + col], h1);
        stcs4((float4*)&out[(size_t)BTOT * HV + rb + col], c1);
    }
}

// ---------------------------------------------------------------------------
// fused fallback (generic weights) — early-exits when identities hold
// ---------------------------------------------------------------------------
__global__ void __launch_bounds__(NT, 1) milstm_kernel(
    const float* __restrict__ inp, const float* __restrict__ skip_c,
    const int* __restrict__ skip_count, const float* __restrict__ h0,
    const float* __restrict__ w_ih, const float* __restrict__ w_hh,
    const float* __restrict__ bias, const float* __restrict__ a_wih,
    const float* __restrict__ a_whh, const float* __restrict__ a_bias,
    float* __restrict__ out) {
    int id_hh = d_id_hh, id_a = d_id_a;
    if (id_hh & id_a) return;
    extern __shared__ char smem[];
    uint32_t* BW0u = (uint32_t*)smem;
    float2*   BW0  = (float2*)smem;
    float* SA0 = (float*)(smem + 2 * BWELE * 4);
    float* SA1 = SA0 + TM * STR;
    int* s_cnt  = (int*)(SA1 + TM * STR);
    int* s_row  = s_cnt + TM;
    int* s_xmax = s_row + TM;

    int tid = threadIdx.x, lane = tid & 31, wid = tid >> 5;
    int warpM = wid & 1, warpN = wid >> 1;
    int base = blockIdx.x * TM;
    int g = lane >> 2, m = lane & 3;

    if (tid == 0) *s_xmax = 0;
    if (tid < TM) {
        int b = d_perm[base + tid];
        s_row[tid] = b;
        s_cnt[tid] = skip_count[b];
    }
    __syncthreads();
    for (int idx = tid; idx < TM * 32; idx += NT) {
        int r = idx >> 5, c = (idx & 31) << 2;
        int b = s_row[r];
        *(float4*)&SA0[r * STR + c] = *(const float4*)&inp[(size_t)b * CINV + c];
        *(float4*)&SA1[r * STR + c] = *(const float4*)&h0[(size_t)b * HV + c];
    }
    if (tid < TM) atomicMax(s_xmax, s_cnt[tid]);
    __syncthreads();

    int rbase = warpM * 32 + g;
    int cnt0 = s_cnt[rbase], cnt1 = s_cnt[rbase + 8];
    int cnt2 = s_cnt[rbase + 16], cnt3 = s_cnt[rbase + 24];
    float denom[32], num[32], ov[32], valpha[32], acc[32];

    #pragma unroll 1
    for (int p = 0; p < 3; p++) {
        stageB(w_ih + p * 128, 3 * HV, BW0u, tid);
        __syncthreads();
        #pragma unroll
        for (int q = 0; q < 32; q++) acc[q] = 0.f;
        gemm_tile(SA0, BW0, acc, warpM, warpN, lane);
        if (!id_hh) {
            __syncthreads();
            stageB(w_hh + p * 128, 3 * HV, BW0u, tid);
            __syncthreads();
            gemm_tile(SA1, BW0, acc, warpM, warpN, lane);
        }
        #pragma unroll
        for (int j = 0; j < 4; j++) {
            int col = warpN * 32 + j * 8 + m * 2;
            float b0 = bias[p * 128 + col], b1 = bias[p * 128 + col + 1];
            #pragma unroll
            for (int mi = 0; mi < 2; mi++) {
                int o0 = mi * 16 + j * 4;
                int rlo = warpM * 32 + mi * 16 + g;
                float h0a = 0.f, h0b = 0.f, h0c = 0.f, h0d = 0.f;
                if (id_hh) {
                    float2 hlo = *(const float2*)&SA1[rlo * STR + col];
                    float2 hhi = *(const float2*)&SA1[(rlo + 8) * STR + col];
                    h0a = hlo.x; h0b = hlo.y; h0c = hhi.x; h0d = hhi.y;
                }
                float z0 = acc[o0 + 0] + b0 + h0a, z1 = acc[o0 + 1] + b1 + h0b;
                float z2 = acc[o0 + 2] + b0 + h0c, z3 = acc[o0 + 3] + b1 + h0d;
                if (p == 0) {
                    denom[o0 + 0] = __expf(sigmf(z0));
                    denom[o0 + 1] = __expf(sigmf(z1));
                    denom[o0 + 2] = __expf(sigmf(z2));
                    denom[o0 + 3] = __expf(sigmf(z3));
                } else if (p == 1) {
                    ov[o0 + 0] = sigmf(z0); ov[o0 + 1] = sigmf(z1);
                    ov[o0 + 2] = sigmf(z2); ov[o0 + 3] = sigmf(z3);
                } else {
                    num[o0 + 0] = tanhf(z0) * denom[o0 + 0];
                    num[o0 + 1] = tanhf(z1) * denom[o0 + 1];
                    num[o0 + 2] = tanhf(z2) * denom[o0 + 2];
                    num[o0 + 3] = tanhf(z3) * denom[o0 + 3];
                }
            }
        }
        __syncthreads();
    }
    stageB(a_wih, HV, BW0u, tid);
    __syncthreads();
    #pragma unroll
    for (int q = 0; q < 32; q++) acc[q] = 0.f;
    gemm_tile(SA0, BW0, acc, warpM, warpN, lane);
    #pragma unroll
    for (int j = 0; j < 4; j++) {
        int col = warpN * 32 + j * 8 + m * 2;
        float b0 = a_bias[col], b1 = a_bias[col + 1];
        #pragma unroll
        for (int mi = 0; mi < 2; mi++) {
            int o0 = mi * 16 + j * 4;
            valpha[o0 + 0] = acc[o0 + 0] + b0;
            valpha[o0 + 1] = acc[o0 + 1] + b1;
            valpha[o0 + 2] = acc[o0 + 2] + b0;
            valpha[o0 + 3] = acc[o0 + 3] + b1;
        }
    }
    __syncthreads();

    if (id_a) {
        #pragma unroll
        for (int q = 0; q < 32; q++) SA0[q * NT + tid] = ov[q];
        int cmax = max(max(cnt0, cnt1), max(cnt2, cnt3));
        cmax = __reduce_max_sync(0xffffffffu, cmax);
        int cnts[4] = {cnt0, cnt1, cnt2, cnt3};
        const float* bp[4] = {
            skip_c + (size_t)s_row[warpM * 32 + g]      * XDIM * HV + warpN * 32 + m * 2,
            skip_c + (size_t)s_row[warpM * 32 + 8 + g]  * XDIM * HV + warpN * 32 + m * 2,
            skip_c + (size_t)s_row[warpM * 32 + 16 + g] * XDIM * HV + warpN * 32 + m * 2,
            skip_c + (size_t)s_row[warpM * 32 + 24 + g] * XDIM * HV + warpN * 32 + m * 2};
        float2 bufA[16], bufB[16];
        auto loadb = [&](float2* d, int xx) {
            size_t off = (size_t)xx * HV;
            #pragma unroll
            for (int r4 = 0; r4 < 4; r4++)
                #pragma unroll
                for (int j = 0; j < 4; j++)
                    d[r4 * 4 + j] = *(const float2*)(bp[r4] + off + j * 8);
        };
        auto accum = [&](const float2* cb, int x) {
            #pragma unroll
            for (int r4 = 0; r4 < 4; r4++) {
                int mi = r4 >> 1, hh = r4 & 1;
                float mk = (x < cnts[r4]) ? 1.f : 0.f;
                #pragma unroll
                for (int j = 0; j < 4; j++) {
                    float2 s = cb[r4 * 4 + j];
                    int e = mi * 16 + j * 4 + hh * 2;
                    float w0 = wfast(s.x + valpha[e + 0]) * mk;
                    float w1 = wfast(s.y + valpha[e + 1]) * mk;
                    denom[e + 0] += w0; denom[e + 1] += w1;
                    num[e + 0] = fmaf(s.x, w0, num[e + 0]);
                    num[e + 1] = fmaf(s.y, w1, num[e + 1]);
                }
            }
        };
        if (cmax > 0) loadb(bufA, 0);
        for (int x = 0; x < cmax; x += 2) {
            if (x + 1 < cmax) loadb(bufB, x + 1);
            accum(bufA, x);
            if (x + 1 >= cmax) break;
            if (x + 2 < cmax) loadb(bufA, x + 2);
            accum(bufB, x + 1);
        }
        #pragma unroll
        for (int q = 0; q < 32; q++) ov[q] = SA0[q * NT + tid];
    } else {
        stageB(a_whh, HV, BW0u, tid);
        __syncthreads();
        int xmax = *s_xmax;
        float* SAb[2] = {SA0, SA1};
        int bufsel = 0;
        if (xmax > 0) {
            #pragma unroll
            for (int i = 0; i < 8; i++) {
                int chunk = tid + i * NT;
                int r = chunk >> 5, cc = (chunk & 31) << 2;
                cpasync16(&SA0[r * STR + cc],
                          &skip_c[((size_t)s_row[r] * XDIM + 0) * HV + cc]);
            }
            cpcommit();
        }
        for (int x = 0; x < xmax; x++) {
            float* S = SAb[bufsel];
            if (x + 1 < xmax) {
                float* Sn = SAb[bufsel ^ 1];
                #pragma unroll
                for (int i = 0; i < 8; i++) {
                    int chunk = tid + i * NT;
                    int r = chunk >> 5, cc = (chunk & 31) << 2;
                    cpasync16(&Sn[r * STR + cc],
                              &skip_c[((size_t)s_row[r] * XDIM + (x + 1)) * HV + cc]);
                }
                cpcommit();
                cpwait<1>();
            } else {
                cpwait<0>();
            }
            __syncthreads();
            #pragma unroll
            for (int q = 0; q < 32; q++) acc[q] = 0.f;
            gemm_tile(S, BW0, acc, warpM, warpN, lane);
            float m0 = (x < cnt0) ? 1.f : 0.f;
            float m1 = (x < cnt1) ? 1.f : 0.f;
            float m2 = (x < cnt2) ? 1.f : 0.f;
            float m3 = (x < cnt3) ? 1.f : 0.f;
            #pragma unroll
            for (int mi = 0; mi < 2; mi++) {
                int rlo = warpM * 32 + mi * 16 + g;
                float mlo = mi ? m2 : m0;
                float mhi = mi ? m3 : m1;
                #pragma unroll
                for (int j = 0; j < 4; j++) {
                    int colb = warpN * 32 + j * 8 + m * 2;
                    float2 slo = *(const float2*)&S[rlo * STR + colb];
                    float2 shi = *(const float2*)&S[(rlo + 8) * STR + colb];
                    int o0 = mi * 16 + j * 4;
                    float e0 = wfast(acc[o0 + 0] + valpha[o0 + 0]) * mlo;
                    float e1 = wfast(acc[o0 + 1] + valpha[o0 + 1]) * mlo;
                    float e2 = wfast(acc[o0 + 2] + valpha[o0 + 2]) * mhi;
                    float e3 = wfast(acc[o0 + 3] + valpha[o0 + 3]) * mhi;
                    denom[o0 + 0] += e0; denom[o0 + 1] += e1;
                    denom[o0 + 2] += e2; denom[o0 + 3] += e3;
                    num[o0 + 0] = fmaf(slo.x, e0, num[o0 + 0]);
                    num[o0 + 1] = fmaf(slo.y, e1, num[o0 + 1]);
                    num[o0 + 2] = fmaf(shi.x, e2, num[o0 + 2]);
                    num[o0 + 3] = fmaf(shi.y, e3, num[o0 + 3]);
                }
            }
            __syncthreads();
            bufsel ^= 1;
        }
    }

    #pragma unroll
    for (int mi = 0; mi < 2; mi++) {
        int rlo = warpM * 32 + mi * 16 + g;
        size_t grow0 = (size_t)s_row[rlo];
        size_t grow1 = (size_t)s_row[rlo + 8];
        #pragma unroll
        for (int j = 0; j < 4; j++) {
            int o0 = mi * 16 + j * 4;
            int colb = warpN * 32 + j * 8 + m * 2;
            float c1a = __fdividef(num[o0 + 0], denom[o0 + 0]);
            float c1b = __fdividef(num[o0 + 1], denom[o0 + 1]);
            float c1c = __fdividef(num[o0 + 2], denom[o0 + 2]);
            float c1d = __fdividef(num[o0 + 3], denom[o0 + 3]);
            *(float2*)&out[grow0 * HV + colb] = make_float2(ov[o0 + 0] * tanhf(c1a), ov[o0 + 1] * tanhf(c1b));
            *(float2*)&out[grow1 * HV + colb] = make_float2(ov[o0 + 2] * tanhf(c1c), ov[o0 + 3] * tanhf(c1d));
            *(float2*)&out[(size_t)BTOT * HV + grow0 * HV + colb] = make_float2(c1a, c1b);
            *(float2*)&out[(size_t)BTOT * HV + grow1 * HV + colb] = make_float2(c1c, c1d);
        }
    }
}

extern "C" void kernel_launch(void* const* d_in, const int* in_sizes, int n_in,
                              void* d_out, int out_size) {
    const float* inp       = (const float*)d_in[0];
    const float* skip_c    = (const float*)d_in[1];
    const int*   skip_cnt  = (const int*)d_in[2];
    const float* h0        = (const float*)d_in[3];
    const float* w_ih      = (const float*)d_in[5];
    const float* w_hh      = (const float*)d_in[6];
    const float* bias      = (const float*)d_in[7];
    const float* a_wih     = (const float*)d_in[8];
    const float* a_whh     = (const float*)d_in[9];
    const float* a_bias    = (const float*)d_in[10];
    float* out = (float*)d_out;

    prep1_kernel<<<P1CTAS, 256>>>(skip_cnt, w_hh, a_whh, w_ih, a_wih);
    prep_scatter_kernel<<<P1CTAS, 256>>>(skip_cnt);

    int smemA = 2 * BWELE * 4 + 2 * TM * STR * 4;
    cudaFuncSetAttribute(phaseA_kernel, cudaFuncAttributeMaxDynamicSharedMemorySize, smemA);
    phaseA_kernel<<<BTOT / TM, NT, smemA>>>(inp, h0, bias, a_bias);

    phaseB_kernel<<<BWARPS / 8, 256>>>(skip_c, skip_cnt, out);

    int smemF = 2 * BWELE * 4 + 2 * TM * STR * 4 + (2 * TM + 2) * 4;
    cudaFuncSetAttribute(milstm_kernel, cudaFuncAttributeMaxDynamicSharedMemorySize, smemF);
    milstm_kernel<<<BTOT / TM, NT, smemF>>>(inp, skip_c, skip_cnt, h0,
                                            w_ih, w_hh, bias, a_wih, a_whh, a_bias, out);
}